// round 4
// baseline (speedup 1.0000x reference)
#include <cuda_runtime.h>
#include <cuda_bf16.h>

#define MAX_BLOCKS 4096

// Scratch in device globals (no allocations allowed).
// g_count is zero-initialized at module load; the last block resets it to 0
// each run, so graph replays are deterministic.
static __device__ float        g_partials[MAX_BLOCKS];
static __device__ unsigned int g_count;

__global__ void __launch_bounds__(256, 8)
wmse_fused_kernel(const float4* __restrict__ pred4,
                  const int4*   __restrict__ lab4,
                  const float*  __restrict__ weights,
                  float* __restrict__ out,
                  long long nv4, long long n) {
    __shared__ float sw[16];
    if (threadIdx.x < 10) sw[threadIdx.x] = weights[threadIdx.x];
    __syncthreads();

    float acc = 0.0f;
    const long long stride = (long long)gridDim.x * blockDim.x;
    // Simple grid-stride loop: MLP_p1 = 2 keeps cross-CTA spread at the
    // ~1.1 floor (B300 spread law); occupancy supplies the memory parallelism.
    for (long long i = (long long)blockIdx.x * blockDim.x + threadIdx.x;
         i < nv4; i += stride) {
        float4 p = pred4[i];
        int4   l = lab4[i];
        float d0 = p.x - (float)l.x;
        float d1 = p.y - (float)l.y;
        float d2 = p.z - (float)l.z;
        float d3 = p.w - (float)l.w;
        acc = fmaf(sw[l.x] * d0, d0, acc);
        acc = fmaf(sw[l.y] * d1, d1, acc);
        acc = fmaf(sw[l.z] * d2, d2, acc);
        acc = fmaf(sw[l.w] * d3, d3, acc);
    }

    // warp reduction
    #pragma unroll
    for (int o = 16; o > 0; o >>= 1)
        acc += __shfl_xor_sync(0xFFFFFFFFu, acc, o);

    __shared__ float warpsum[8];
    int lane = threadIdx.x & 31;
    int wid  = threadIdx.x >> 5;
    if (lane == 0) warpsum[wid] = acc;
    __syncthreads();

    __shared__ bool s_last;
    if (wid == 0) {
        float v = (lane < 8) ? warpsum[lane] : 0.0f;
        #pragma unroll
        for (int o = 4; o > 0; o >>= 1)
            v += __shfl_xor_sync(0xFFFFFFFFu, v, o);
        if (lane == 0) {
            g_partials[blockIdx.x] = v;
            __threadfence();
            unsigned int done = atomicAdd(&g_count, 1u);
            s_last = (done == gridDim.x - 1);
        }
    }
    __syncthreads();

    // Last block to finish sums the partials and writes the result.
    if (s_last) {
        double dacc = 0.0;
        for (unsigned int j = threadIdx.x; j < gridDim.x; j += blockDim.x)
            dacc += (double)g_partials[j];
        #pragma unroll
        for (int o = 16; o > 0; o >>= 1)
            dacc += __shfl_xor_sync(0xFFFFFFFFu, dacc, o);
        __shared__ double dwarp[8];
        if (lane == 0) dwarp[wid] = dacc;
        __syncthreads();
        if (wid == 0) {
            double dv = (lane < 8) ? dwarp[lane] : 0.0;
            #pragma unroll
            for (int o = 4; o > 0; o >>= 1)
                dv += __shfl_xor_sync(0xFFFFFFFFu, dv, o);
            if (lane == 0) {
                *out = (float)(dv / (double)n);
                g_count = 0;  // reset for next graph replay
            }
        }
    }
}

extern "C" void kernel_launch(void* const* d_in, const int* in_sizes, int n_in,
                              void* d_out, int out_size) {
    const float* pred    = (const float*)d_in[0];
    const int*   labels  = (const int*)d_in[1];
    const float* weights = (const float*)d_in[2];
    float* out = (float*)d_out;

    long long n   = (long long)in_sizes[0];
    long long nv4 = n >> 2;   // N = 2^25, divisible by 4

    const int threads = 256;
    int blocks = 148 * 16;  // 2368 blocks, same as R1's fast configuration
    long long needed = (nv4 + threads - 1) / threads;
    if ((long long)blocks > needed) blocks = (int)needed;
    if (blocks > MAX_BLOCKS) blocks = MAX_BLOCKS;

    wmse_fused_kernel<<<blocks, threads>>>(
        (const float4*)pred, (const int4*)labels, weights, out, nv4, n);
}

// round 9
// speedup vs baseline: 1.1007x; 1.1007x over previous
#include <cuda_runtime.h>
#include <cuda_bf16.h>

// Scalar accumulator in device global (no allocations allowed).
// Zero at module load; finalize kernel resets it to 0 after each use,
// so every graph replay sees g_accum == 0 on entry to the reduce kernel.
static __device__ double g_accum;

__global__ void __launch_bounds__(256, 8)
wmse_reduce_kernel(const float4* __restrict__ pred4,
                   const int4*   __restrict__ lab4,
                   const float*  __restrict__ weights,
                   long long nv4) {
    __shared__ float sw[16];
    if (threadIdx.x < 10) sw[threadIdx.x] = weights[threadIdx.x];
    __syncthreads();

    float acc = 0.0f;
    const long long stride = (long long)gridDim.x * blockDim.x;
    for (long long i = (long long)blockIdx.x * blockDim.x + threadIdx.x;
         i < nv4; i += stride) {
        float4 p = pred4[i];
        int4   l = lab4[i];
        float d0 = p.x - (float)l.x;
        float d1 = p.y - (float)l.y;
        float d2 = p.z - (float)l.z;
        float d3 = p.w - (float)l.w;
        acc = fmaf(sw[l.x] * d0, d0, acc);
        acc = fmaf(sw[l.y] * d1, d1, acc);
        acc = fmaf(sw[l.z] * d2, d2, acc);
        acc = fmaf(sw[l.w] * d3, d3, acc);
    }

    // warp reduction
    #pragma unroll
    for (int o = 16; o > 0; o >>= 1)
        acc += __shfl_xor_sync(0xFFFFFFFFu, acc, o);

    __shared__ float warpsum[8];
    int lane = threadIdx.x & 31;
    int wid  = threadIdx.x >> 5;
    if (lane == 0) warpsum[wid] = acc;
    __syncthreads();

    if (wid == 0) {
        float v = (lane < 8) ? warpsum[lane] : 0.0f;
        #pragma unroll
        for (int o = 4; o > 0; o >>= 1)
            v += __shfl_xor_sync(0xFFFFFFFFu, v, o);
        if (lane == 0)
            atomicAdd(&g_accum, (double)v);   // fire-and-forget, REDG-class
    }
}

__global__ void wmse_finalize_kernel(float* out, long long n) {
    if (threadIdx.x == 0) {
        *out = (float)(g_accum / (double)n);
        g_accum = 0.0;   // reset for the next graph replay (deterministic)
    }
}

extern "C" void kernel_launch(void* const* d_in, const int* in_sizes, int n_in,
                              void* d_out, int out_size) {
    const float* pred    = (const float*)d_in[0];
    const int*   labels  = (const int*)d_in[1];
    const float* weights = (const float*)d_in[2];
    float* out = (float*)d_out;

    long long n   = (long long)in_sizes[0];
    long long nv4 = n >> 2;   // N = 2^25, divisible by 4

    const int threads = 256;
    int blocks = 148 * 16;  // 2368 blocks — R1's fast configuration
    long long needed = (nv4 + threads - 1) / threads;
    if ((long long)blocks > needed) blocks = (int)needed;

    wmse_reduce_kernel<<<blocks, threads>>>(
        (const float4*)pred, (const int4*)labels, weights, nv4);

    wmse_finalize_kernel<<<1, 32>>>(out, n);
}